// round 3
// baseline (speedup 1.0000x reference)
#include <cuda_runtime.h>

// Problem constants
#define Bq 4
#define Hq 16
#define Sq 2048
#define Dq 128

// Tiling: 128x128 flash tile, 256 threads, 8x8 register microtile per thread
#define BM 128
#define BN 128
#define NT 256
#define QS 132                     // smem row stride (floats), float4-aligned
#define SMEM_FLOATS (3 * 128 * QS) // Qs + KV(shared) + Ps

#define LOG2E 1.44269504088896340736f

typedef unsigned long long u64;

struct F4 { float f[4]; };

static __device__ __forceinline__ F4 ldf4(const float* p) {
    float4 t = *(const float4*)p;
    F4 r; r.f[0] = t.x; r.f[1] = t.y; r.f[2] = t.z; r.f[3] = t.w;
    return r;
}

// Packed dual-FMA: d = a*b + c (elementwise on 2 floats). Only reachable via PTX.
static __device__ __forceinline__ float2 ffma2(float2 a, float2 b, float2 c) {
    float2 d;
    asm("fma.rn.f32x2 %0, %1, %2, %3;"
        : "=l"(reinterpret_cast<u64&>(d))
        : "l"(reinterpret_cast<u64&>(a)),
          "l"(reinterpret_cast<u64&>(b)),
          "l"(reinterpret_cast<u64&>(c)));
    return d;
}
static __device__ __forceinline__ float2 fmul2(float2 a, float2 b) {
    float2 d;
    asm("mul.rn.f32x2 %0, %1, %2;"
        : "=l"(reinterpret_cast<u64&>(d))
        : "l"(reinterpret_cast<u64&>(a)),
          "l"(reinterpret_cast<u64&>(b)));
    return d;
}
static __device__ __forceinline__ float ex2(float x) {
    float y;
    asm("ex2.approx.f32 %0, %1;" : "=f"(y) : "f"(x));
    return y;
}

__global__ __launch_bounds__(NT, 1)
void attn_fp32x2_kernel(const float* __restrict__ q,
                        const float* __restrict__ k,
                        const float* __restrict__ v,
                        const float* __restrict__ scale,
                        float* __restrict__ out)
{
    extern __shared__ float sm[];
    float* Qs  = sm;                 // [128][QS]  Q tile
    float* KVs = sm + 128 * QS;      // K^T [k][t] then V [t][d] (reused buffer)
    float* Ps  = sm + 2 * 128 * QS;  // [128][QS]  P tile

    const int tid = threadIdx.x;
    const int tx  = tid & 15;        // column group
    const int ty  = tid >> 4;        // row group; thread rows = ty + 16*i

    const int tile = blockIdx.x;     // 0..15
    const int bh   = blockIdx.y;     // 0..63

    const size_t base = (size_t)bh * Sq * Dq;
    const float* Qg = q + base + (size_t)tile * BM * Dq;
    float*       Og = out + base + (size_t)tile * BM * Dq;
    const float  scL = scale[bh] * LOG2E;   // work in log2 domain

    // ---- Load Q tile (coalesced) ----
    #pragma unroll
    for (int c = tid; c < BM * Dq / 4; c += NT) {
        int r = c >> 5, k4 = c & 31;
        float4 g = *(const float4*)(Qg + (size_t)r * Dq + k4 * 4);
        *(float4*)&Qs[r * QS + k4 * 4] = g;
    }

    // ---- State ----
    float2 o[8][4];                   // O rows ty+16i, cols {tx*4..+3, 64+tx*4..+3}
    float  mrow[8], lrow[8];
    const float NEG_INF = __int_as_float(0xff800000);
    #pragma unroll
    for (int i = 0; i < 8; i++) {
        mrow[i] = NEG_INF; lrow[i] = 0.f;
        #pragma unroll
        for (int j = 0; j < 4; j++) o[i][j] = make_float2(0.f, 0.f);
    }

    for (int n = 0; n < Sq / BN; ++n) {
        // ---- Load K transposed into KVs[k][t] (conflict-free STS) ----
        const float* Kg = k + base + (size_t)n * BN * Dq;
        #pragma unroll
        for (int c = tid; c < BN * Dq / 4; c += NT) {
            int t = c & 127, k4 = c >> 7;
            float4 g = *(const float4*)(Kg + (size_t)t * Dq + k4 * 4);
            KVs[(k4 * 4 + 0) * QS + t] = g.x;
            KVs[(k4 * 4 + 1) * QS + t] = g.y;
            KVs[(k4 * 4 + 2) * QS + t] = g.z;
            KVs[(k4 * 4 + 3) * QS + t] = g.w;
        }
        __syncthreads();

        // ---- S = Q @ K^T : 8x8 microtile, packed f32x2 on column pairs ----
        float2 acc[8][4];
        #pragma unroll
        for (int i = 0; i < 8; i++)
            #pragma unroll
            for (int j = 0; j < 4; j++) acc[i][j] = make_float2(0.f, 0.f);

        #pragma unroll 2
        for (int k4 = 0; k4 < Dq / 4; ++k4) {
            F4 a4[8];
            #pragma unroll
            for (int i = 0; i < 8; i++)
                a4[i] = ldf4(&Qs[(ty + 16 * i) * QS + k4 * 4]);   // 1-wavefront broadcast
            #pragma unroll
            for (int kk = 0; kk < 4; kk++) {
                int kr = k4 * 4 + kk;
                F4 bA = ldf4(&KVs[kr * QS + tx * 4]);            // 2-wavefront, no conflicts
                F4 bB = ldf4(&KVs[kr * QS + 64 + tx * 4]);
                float2 bA0 = make_float2(bA.f[0], bA.f[1]);
                float2 bA1 = make_float2(bA.f[2], bA.f[3]);
                float2 bB0 = make_float2(bB.f[0], bB.f[1]);
                float2 bB1 = make_float2(bB.f[2], bB.f[3]);
                #pragma unroll
                for (int i = 0; i < 8; i++) {
                    float2 as = make_float2(a4[i].f[kk], a4[i].f[kk]);
                    acc[i][0] = ffma2(as, bA0, acc[i][0]);
                    acc[i][1] = ffma2(as, bA1, acc[i][1]);
                    acc[i][2] = ffma2(as, bB0, acc[i][2]);
                    acc[i][3] = ffma2(as, bB1, acc[i][3]);
                }
            }
        }

        // ---- Online softmax (log2 domain), write P tile ----
        #pragma unroll
        for (int i = 0; i < 8; i++) {
            float z[8];
            #pragma unroll
            for (int j = 0; j < 4; j++) {
                z[2 * j + 0] = acc[i][j].x * scL;
                z[2 * j + 1] = acc[i][j].y * scL;
            }
            float rmax = z[0];
            #pragma unroll
            for (int j = 1; j < 8; j++) rmax = fmaxf(rmax, z[j]);
            #pragma unroll
            for (int off = 8; off; off >>= 1)
                rmax = fmaxf(rmax, __shfl_xor_sync(0xffffffffu, rmax, off));
            float mnew = fmaxf(mrow[i], rmax);

            float p[8], rsum = 0.f;
            #pragma unroll
            for (int j = 0; j < 8; j++) { p[j] = ex2(z[j] - mnew); rsum += p[j]; }
            #pragma unroll
            for (int off = 8; off; off >>= 1)
                rsum += __shfl_xor_sync(0xffffffffu, rsum, off);

            float alpha = ex2(mrow[i] - mnew);
            mrow[i] = mnew;
            lrow[i] = lrow[i] * alpha + rsum;
            float2 al = make_float2(alpha, alpha);
            #pragma unroll
            for (int j = 0; j < 4; j++) o[i][j] = fmul2(o[i][j], al);

            float4 pa, pb;
            pa.x = p[0]; pa.y = p[1]; pa.z = p[2]; pa.w = p[3];
            pb.x = p[4]; pb.y = p[5]; pb.z = p[6]; pb.w = p[7];
            *(float4*)&Ps[(ty + 16 * i) * QS + tx * 4]      = pa;
            *(float4*)&Ps[(ty + 16 * i) * QS + 64 + tx * 4] = pb;
        }
        __syncthreads();   // all P written, all K reads done -> KVs reusable

        // ---- Load V into KVs[t][d] (coalesced) ----
        const float* Vg = v + base + (size_t)n * BN * Dq;
        #pragma unroll
        for (int c = tid; c < BN * Dq / 4; c += NT) {
            int t = c >> 5, c4 = c & 31;
            float4 g = *(const float4*)(Vg + (size_t)t * Dq + c4 * 4);
            *(float4*)&KVs[t * QS + c4 * 4] = g;
        }
        __syncthreads();

        // ---- O += P @ V : same microtile structure ----
        #pragma unroll 2
        for (int t4 = 0; t4 < BN / 4; ++t4) {
            F4 p4[8];
            #pragma unroll
            for (int i = 0; i < 8; i++)
                p4[i] = ldf4(&Ps[(ty + 16 * i) * QS + t4 * 4]);  // broadcast
            #pragma unroll
            for (int tt = 0; tt < 4; tt++) {
                int t = t4 * 4 + tt;
                F4 vA = ldf4(&KVs[t * QS + tx * 4]);
                F4 vB = ldf4(&KVs[t * QS + 64 + tx * 4]);
                float2 vA0 = make_float2(vA.f[0], vA.f[1]);
                float2 vA1 = make_float2(vA.f[2], vA.f[3]);
                float2 vB0 = make_float2(vB.f[0], vB.f[1]);
                float2 vB1 = make_float2(vB.f[2], vB.f[3]);
                #pragma unroll
                for (int i = 0; i < 8; i++) {
                    float2 ps = make_float2(p4[i].f[tt], p4[i].f[tt]);
                    o[i][0] = ffma2(ps, vA0, o[i][0]);
                    o[i][1] = ffma2(ps, vA1, o[i][1]);
                    o[i][2] = ffma2(ps, vB0, o[i][2]);
                    o[i][3] = ffma2(ps, vB1, o[i][3]);
                }
            }
        }
        __syncthreads();   // before next tile overwrites KVs
    }

    // ---- Epilogue: normalize and store ----
    #pragma unroll
    for (int i = 0; i < 8; i++) {
        float inv = 1.0f / lrow[i];
        float2 iv = make_float2(inv, inv);
        float2 r0 = fmul2(o[i][0], iv), r1 = fmul2(o[i][1], iv);
        float2 r2 = fmul2(o[i][2], iv), r3 = fmul2(o[i][3], iv);
        float* orow = Og + (size_t)(ty + 16 * i) * Dq;
        float4 u; u.x = r0.x; u.y = r0.y; u.z = r1.x; u.w = r1.y;
        float4 w; w.x = r2.x; w.y = r2.y; w.z = r3.x; w.w = r3.y;
        *(float4*)(orow + tx * 4)      = u;
        *(float4*)(orow + 64 + tx * 4) = w;
    }
}

extern "C" void kernel_launch(void* const* d_in, const int* in_sizes, int n_in,
                              void* d_out, int out_size)
{
    const float* q     = (const float*)d_in[0];
    const float* k     = (const float*)d_in[1];
    const float* v     = (const float*)d_in[2];
    const float* scale = (const float*)d_in[3];
    float* out = (float*)d_out;

    const int smem_bytes = SMEM_FLOATS * (int)sizeof(float);
    cudaFuncSetAttribute(attn_fp32x2_kernel,
                         cudaFuncAttributeMaxDynamicSharedMemorySize, smem_bytes);

    dim3 grid(Sq / BM, Bq * Hq);
    attn_fp32x2_kernel<<<grid, NT, smem_bytes>>>(q, k, v, scale, out);
}

// round 5
// speedup vs baseline: 2.6013x; 2.6013x over previous
#include <cuda_runtime.h>
#include <cuda_fp16.h>

typedef unsigned int u32;

#define NT  256
#define BM  128
#define BN  64
#define Dh  128
#define SEQ 2048
#define NIT (SEQ / BN)
#define LOG2E 1.44269504088896340736f

// ---- smem byte layout ----
#define QH_OFF 0
#define QL_OFF 32768
#define K_OFF  65536         // + buf*32768 ; lo at +16384
#define V_OFF  131072        // + buf*32768 ; lo at +16384
#define SMEM_BYTES 196608

static __device__ __forceinline__ u32 cvta_smem(const void* p) {
    u32 a;
    asm("{ .reg .u64 t; cvta.to.shared.u64 t, %1; cvt.u32.u64 %0, t; }" : "=r"(a) : "l"(p));
    return a;
}
// swizzled byte offset of 16B chunk `ch` (0..15) in row `row` (256B rows)
static __device__ __forceinline__ u32 swoff(int row, int ch) {
    return (u32)(row * 256 + ((ch ^ (row & 7)) << 4));
}
static __device__ __forceinline__ float ex2f(float x) {
    float y; asm("ex2.approx.f32 %0, %1;" : "=f"(y) : "f"(x)); return y;
}
// split (x0,x1) into packed f16 hi + f16 residual lo
static __device__ __forceinline__ void split2(float x0, float x1, u32& hi, u32& lo) {
    __half2 h = __floats2half2_rn(x0, x1);
    float2  b = __half22float2(h);
    __half2 l = __floats2half2_rn(x0 - b.x, x1 - b.y);
    hi = *(u32*)&h; lo = *(u32*)&l;
}

static __device__ __forceinline__ void ldm4(u32 addr, u32& r0, u32& r1, u32& r2, u32& r3) {
    asm volatile("ldmatrix.sync.aligned.m8n8.x4.shared.b16 {%0,%1,%2,%3}, [%4];"
                 : "=r"(r0), "=r"(r1), "=r"(r2), "=r"(r3) : "r"(addr));
}
static __device__ __forceinline__ void ldm4t(u32 addr, u32& r0, u32& r1, u32& r2, u32& r3) {
    asm volatile("ldmatrix.sync.aligned.m8n8.x4.trans.shared.b16 {%0,%1,%2,%3}, [%4];"
                 : "=r"(r0), "=r"(r1), "=r"(r2), "=r"(r3) : "r"(addr));
}
static __device__ __forceinline__ void mma(float* d, u32 a0, u32 a1, u32 a2, u32 a3, u32 b0, u32 b1) {
    asm volatile("mma.sync.aligned.m16n8k16.row.col.f32.f16.f16.f32 "
                 "{%0,%1,%2,%3}, {%4,%5,%6,%7}, {%8,%9}, {%0,%1,%2,%3};"
                 : "+f"(d[0]), "+f"(d[1]), "+f"(d[2]), "+f"(d[3])
                 : "r"(a0), "r"(a1), "r"(a2), "r"(a3), "r"(b0), "r"(b1));
}

// convert a 64x128 f32 tile -> swizzled f16 hi/lo in smem
static __device__ __forceinline__ void conv_tile(const float* __restrict__ src,
                                                 char* dh, char* dl, int tid) {
    #pragma unroll
    for (int p = 0; p < 4; p++) {
        int idx = tid + p * 256;
        int row = idx >> 4, ch = idx & 15;
        const float* s = src + (size_t)row * Dh + ch * 8;
        float4 a = *(const float4*)s;
        float4 b = *(const float4*)(s + 4);
        u32 h0, l0, h1, l1, h2, l2, h3, l3;
        split2(a.x, a.y, h0, l0); split2(a.z, a.w, h1, l1);
        split2(b.x, b.y, h2, l2); split2(b.z, b.w, h3, l3);
        u32 off = swoff(row, ch);
        *(uint4*)(dh + off) = make_uint4(h0, h1, h2, h3);
        *(uint4*)(dl + off) = make_uint4(l0, l1, l2, l3);
    }
}

__global__ __launch_bounds__(NT, 1)
void attn_hmma(const float* __restrict__ qg, const float* __restrict__ kg,
               const float* __restrict__ vg, const float* __restrict__ scg,
               float* __restrict__ og)
{
    extern __shared__ char sm[];
    const u32 smb = cvta_smem(sm);
    const int tid = threadIdx.x, lane = tid & 31, wid = tid >> 5;

    const int tile = blockIdx.x;
    const int bh   = blockIdx.y;
    const size_t base = (size_t)bh * SEQ * Dh;
    const float* Qg = qg + base + (size_t)tile * BM * Dh;
    const float* Kg = kg + base;
    const float* Vg = vg + base;
    float*       Og = og + base + (size_t)tile * BM * Dh;
    const float scL = scg[bh] * LOG2E;

    // ---- prologue: Q (scale folded) + tile 0 ----
    #pragma unroll
    for (int p = 0; p < 8; p++) {
        int idx = tid + p * 256;
        int row = idx >> 4, ch = idx & 15;
        const float* s = Qg + (size_t)row * Dh + ch * 8;
        float4 a = *(const float4*)s;
        float4 b = *(const float4*)(s + 4);
        u32 h0, l0, h1, l1, h2, l2, h3, l3;
        split2(a.x * scL, a.y * scL, h0, l0); split2(a.z * scL, a.w * scL, h1, l1);
        split2(b.x * scL, b.y * scL, h2, l2); split2(b.z * scL, b.w * scL, h3, l3);
        u32 off = swoff(row, ch);
        *(uint4*)(sm + QH_OFF + off) = make_uint4(h0, h1, h2, h3);
        *(uint4*)(sm + QL_OFF + off) = make_uint4(l0, l1, l2, l3);
    }
    conv_tile(Kg, sm + K_OFF, sm + K_OFF + 16384, tid);
    conv_tile(Vg, sm + V_OFF, sm + V_OFF + 16384, tid);
    __syncthreads();

    // ---- per-warp state ----
    float oacc[16][4];
    #pragma unroll
    for (int f = 0; f < 16; f++)
        #pragma unroll
        for (int j = 0; j < 4; j++) oacc[f][j] = 0.f;
    float mA = -1e30f, mB = -1e30f, lA = 0.f, lB = 0.f;

    const int wr0 = wid * 16;
    const int qrow    = wr0 + (lane & 15);        // A-frag source row
    const int qchh    = lane >> 4;                // A-frag k-half
    const int kn      = (lane & 7) + ((lane >> 4) << 3);          // B-frag n row
    const int kchh    = (lane >> 3) & 1;                          // B-frag k-half
    const int vkey    = (lane & 7) + (((lane >> 3) & 1) << 3);    // V trans source row
    const int vchh    = lane >> 4;                                // V d-chunk half

    #pragma unroll 1
    for (int n = 0; n < NIT; n++) {
        const int buf = n & 1;
        const u32 khb = smb + K_OFF + buf * 32768;
        const u32 klb = khb + 16384;
        const u32 vhb = smb + V_OFF + buf * 32768;
        const u32 vlb = vhb + 16384;

        // ---- S = (Qh+Ql)(Kh+Kl)^T, 3 products into same f32 acc ----
        float sacc[8][4];
        #pragma unroll
        for (int f = 0; f < 8; f++)
            #pragma unroll
            for (int j = 0; j < 4; j++) sacc[f][j] = 0.f;

        #pragma unroll
        for (int kk = 0; kk < 8; kk++) {
            u32 qoff = swoff(qrow, kk * 2 + qchh);
            u32 qh0, qh1, qh2, qh3, ql0, ql1, ql2, ql3;
            ldm4(smb + QH_OFF + qoff, qh0, qh1, qh2, qh3);
            ldm4(smb + QL_OFF + qoff, ql0, ql1, ql2, ql3);
            #pragma unroll
            for (int jp = 0; jp < 4; jp++) {
                u32 koff = swoff(jp * 16 + kn, kk * 2 + kchh);
                u32 kb0, kb1, kb2, kb3, lb0, lb1, lb2, lb3;
                ldm4(khb + koff, kb0, kb1, kb2, kb3);
                ldm4(klb + koff, lb0, lb1, lb2, lb3);
                mma(sacc[jp * 2],     qh0, qh1, qh2, qh3, kb0, kb1);
                mma(sacc[jp * 2],     qh0, qh1, qh2, qh3, lb0, lb1);
                mma(sacc[jp * 2],     ql0, ql1, ql2, ql3, kb0, kb1);
                mma(sacc[jp * 2 + 1], qh0, qh1, qh2, qh3, kb2, kb3);
                mma(sacc[jp * 2 + 1], qh0, qh1, qh2, qh3, lb2, lb3);
                mma(sacc[jp * 2 + 1], ql0, ql1, ql2, ql3, kb2, kb3);
            }
        }

        // ---- online softmax (log2 domain; scale folded into Q) ----
        float rmaxA = -1e30f, rmaxB = -1e30f;
        #pragma unroll
        for (int f = 0; f < 8; f++) {
            rmaxA = fmaxf(rmaxA, fmaxf(sacc[f][0], sacc[f][1]));
            rmaxB = fmaxf(rmaxB, fmaxf(sacc[f][2], sacc[f][3]));
        }
        rmaxA = fmaxf(rmaxA, __shfl_xor_sync(0xffffffffu, rmaxA, 1));
        rmaxA = fmaxf(rmaxA, __shfl_xor_sync(0xffffffffu, rmaxA, 2));
        rmaxB = fmaxf(rmaxB, __shfl_xor_sync(0xffffffffu, rmaxB, 1));
        rmaxB = fmaxf(rmaxB, __shfl_xor_sync(0xffffffffu, rmaxB, 2));

        float mnA = fmaxf(mA, rmaxA), mnB = fmaxf(mB, rmaxB);
        float aA = ex2f(mA - mnA), aB = ex2f(mB - mnB);
        mA = mnA; mB = mnB;

        u32 ph[4][4], pl[4][4];
        float sA = 0.f, sB = 0.f;
        #pragma unroll
        for (int kk = 0; kk < 4; kk++) {
            float p0 = ex2f(sacc[2 * kk][0] - mnA);
            float p1 = ex2f(sacc[2 * kk][1] - mnA);
            float p2 = ex2f(sacc[2 * kk][2] - mnB);
            float p3 = ex2f(sacc[2 * kk][3] - mnB);
            float p4 = ex2f(sacc[2 * kk + 1][0] - mnA);
            float p5 = ex2f(sacc[2 * kk + 1][1] - mnA);
            float p6 = ex2f(sacc[2 * kk + 1][2] - mnB);
            float p7 = ex2f(sacc[2 * kk + 1][3] - mnB);
            sA += (p0 + p1) + (p4 + p5);
            sB += (p2 + p3) + (p6 + p7);
            split2(p0, p1, ph[kk][0], pl[kk][0]);
            split2(p2, p3, ph[kk][1], pl[kk][1]);
            split2(p4, p5, ph[kk][2], pl[kk][2]);
            split2(p6, p7, ph[kk][3], pl[kk][3]);
        }
        sA += __shfl_xor_sync(0xffffffffu, sA, 1);
        sA += __shfl_xor_sync(0xffffffffu, sA, 2);
        sB += __shfl_xor_sync(0xffffffffu, sB, 1);
        sB += __shfl_xor_sync(0xffffffffu, sB, 2);
        lA = lA * aA + sA;
        lB = lB * aB + sB;

        #pragma unroll
        for (int f = 0; f < 16; f++) {
            oacc[f][0] *= aA; oacc[f][1] *= aA;
            oacc[f][2] *= aB; oacc[f][3] *= aB;
        }

        // ---- O += (Ph+Pl)(Vh+Vl), 3 products ----
        #pragma unroll
        for (int kk = 0; kk < 4; kk++) {
            #pragma unroll
            for (int dp = 0; dp < 8; dp++) {
                u32 voff = swoff(kk * 16 + vkey, dp * 2 + vchh);
                u32 vb0, vb1, vb2, vb3, wb0, wb1, wb2, wb3;
                ldm4t(vhb + voff, vb0, vb1, vb2, vb3);
                ldm4t(vlb + voff, wb0, wb1, wb2, wb3);
                mma(oacc[2 * dp],     ph[kk][0], ph[kk][1], ph[kk][2], ph[kk][3], vb0, vb1);
                mma(oacc[2 * dp],     ph[kk][0], ph[kk][1], ph[kk][2], ph[kk][3], wb0, wb1);
                mma(oacc[2 * dp],     pl[kk][0], pl[kk][1], pl[kk][2], pl[kk][3], vb0, vb1);
                mma(oacc[2 * dp + 1], ph[kk][0], ph[kk][1], ph[kk][2], ph[kk][3], vb2, vb3);
                mma(oacc[2 * dp + 1], ph[kk][0], ph[kk][1], ph[kk][2], ph[kk][3], wb2, wb3);
                mma(oacc[2 * dp + 1], pl[kk][0], pl[kk][1], pl[kk][2], pl[kk][3], vb2, vb3);
            }
        }

        __syncthreads();
        if (n + 1 < NIT) {
            conv_tile(Kg + (size_t)(n + 1) * BN * Dh,
                      sm + K_OFF + (buf ^ 1) * 32768,
                      sm + K_OFF + (buf ^ 1) * 32768 + 16384, tid);
            conv_tile(Vg + (size_t)(n + 1) * BN * Dh,
                      sm + V_OFF + (buf ^ 1) * 32768,
                      sm + V_OFF + (buf ^ 1) * 32768 + 16384, tid);
        }
        __syncthreads();
    }

    // ---- epilogue ----
    const float iA = 1.f / lA, iB = 1.f / lB;
    const int ra = wr0 + (lane >> 2);
    const int rb = ra + 8;
    const int cb = 2 * (lane & 3);
    #pragma unroll
    for (int f = 0; f < 16; f++) {
        float2 va; va.x = oacc[f][0] * iA; va.y = oacc[f][1] * iA;
        float2 vb; vb.x = oacc[f][2] * iB; vb.y = oacc[f][3] * iB;
        *(float2*)(Og + (size_t)ra * Dh + f * 8 + cb) = va;
        *(float2*)(Og + (size_t)rb * Dh + f * 8 + cb) = vb;
    }
}

extern "C" void kernel_launch(void* const* d_in, const int* in_sizes, int n_in,
                              void* d_out, int out_size)
{
    const float* q     = (const float*)d_in[0];
    const float* k     = (const float*)d_in[1];
    const float* v     = (const float*)d_in[2];
    const float* scale = (const float*)d_in[3];
    float* out = (float*)d_out;

    cudaFuncSetAttribute(attn_hmma, cudaFuncAttributeMaxDynamicSharedMemorySize, SMEM_BYTES);
    dim3 grid(SEQ / BM, 4 * 16);
    attn_hmma<<<grid, NT, SMEM_BYTES>>>(q, k, v, scale, out);
}

// round 6
// speedup vs baseline: 3.5231x; 1.3544x over previous
#include <cuda_runtime.h>
#include <cuda_fp16.h>

typedef unsigned int u32;

#define NT  256
#define BM  128
#define BN  64
#define Dh  128
#define SEQ 2048
#define NIT (SEQ / BN)
#define LOG2E 1.44269504088896340736f

// ---- smem byte layout ----
#define QH_OFF 0
#define QL_OFF 32768
#define K_OFF  65536          // + buf*32768 ; lo at +16384
#define V_OFF  131072         // + buf*16384 (hi only)
#define SMEM_BYTES 163840

static __device__ __forceinline__ u32 cvta_smem(const void* p) {
    u32 a;
    asm("{ .reg .u64 t; cvta.to.shared.u64 t, %1; cvt.u32.u64 %0, t; }" : "=r"(a) : "l"(p));
    return a;
}
// swizzled byte offset of 16B chunk `ch` (0..15) in row `row` (256B rows)
static __device__ __forceinline__ u32 swoff(int row, int ch) {
    return (u32)(row * 256 + ((ch ^ (row & 7)) << 4));
}
static __device__ __forceinline__ float ex2f(float x) {
    float y; asm("ex2.approx.f32 %0, %1;" : "=f"(y) : "f"(x)); return y;
}
static __device__ __forceinline__ u32 pack2(float x0, float x1) {
    __half2 h = __floats2half2_rn(x0, x1);
    return *(u32*)&h;
}
// split (x0,x1) into packed f16 hi + f16 residual lo
static __device__ __forceinline__ void split2(float x0, float x1, u32& hi, u32& lo) {
    __half2 h = __floats2half2_rn(x0, x1);
    float2  b = __half22float2(h);
    __half2 l = __floats2half2_rn(x0 - b.x, x1 - b.y);
    hi = *(u32*)&h; lo = *(u32*)&l;
}

static __device__ __forceinline__ void ldm4(u32 addr, u32& r0, u32& r1, u32& r2, u32& r3) {
    asm volatile("ldmatrix.sync.aligned.m8n8.x4.shared.b16 {%0,%1,%2,%3}, [%4];"
                 : "=r"(r0), "=r"(r1), "=r"(r2), "=r"(r3) : "r"(addr));
}
static __device__ __forceinline__ void ldm4t(u32 addr, u32& r0, u32& r1, u32& r2, u32& r3) {
    asm volatile("ldmatrix.sync.aligned.m8n8.x4.trans.shared.b16 {%0,%1,%2,%3}, [%4];"
                 : "=r"(r0), "=r"(r1), "=r"(r2), "=r"(r3) : "r"(addr));
}
static __device__ __forceinline__ void mma(float* d, u32 a0, u32 a1, u32 a2, u32 a3, u32 b0, u32 b1) {
    asm volatile("mma.sync.aligned.m16n8k16.row.col.f32.f16.f16.f32 "
                 "{%0,%1,%2,%3}, {%4,%5,%6,%7}, {%8,%9}, {%0,%1,%2,%3};"
                 : "+f"(d[0]), "+f"(d[1]), "+f"(d[2]), "+f"(d[3])
                 : "r"(a0), "r"(a1), "r"(a2), "r"(a3), "r"(b0), "r"(b1));
}

// convert a 64x128 f32 tile -> swizzled f16 hi/lo in smem (K: split)
static __device__ __forceinline__ void conv_k(const float* __restrict__ src,
                                              char* dh, char* dl, int tid) {
    #pragma unroll
    for (int p = 0; p < 4; p++) {
        int idx = tid + p * 256;
        int row = idx >> 4, ch = idx & 15;
        const float* s = src + (size_t)row * Dh + ch * 8;
        float4 a = *(const float4*)s;
        float4 b = *(const float4*)(s + 4);
        u32 h0, l0, h1, l1, h2, l2, h3, l3;
        split2(a.x, a.y, h0, l0); split2(a.z, a.w, h1, l1);
        split2(b.x, b.y, h2, l2); split2(b.z, b.w, h3, l3);
        u32 off = swoff(row, ch);
        *(uint4*)(dh + off) = make_uint4(h0, h1, h2, h3);
        *(uint4*)(dl + off) = make_uint4(l0, l1, l2, l3);
    }
}
// convert a 64x128 f32 tile -> swizzled f16 (V: hi only)
static __device__ __forceinline__ void conv_v(const float* __restrict__ src,
                                              char* dh, int tid) {
    #pragma unroll
    for (int p = 0; p < 4; p++) {
        int idx = tid + p * 256;
        int row = idx >> 4, ch = idx & 15;
        const float* s = src + (size_t)row * Dh + ch * 8;
        float4 a = *(const float4*)s;
        float4 b = *(const float4*)(s + 4);
        u32 off = swoff(row, ch);
        *(uint4*)(dh + off) = make_uint4(pack2(a.x, a.y), pack2(a.z, a.w),
                                         pack2(b.x, b.y), pack2(b.z, b.w));
    }
}

__global__ __launch_bounds__(NT, 1)
void attn_hmma(const float* __restrict__ qg, const float* __restrict__ kg,
               const float* __restrict__ vg, const float* __restrict__ scg,
               float* __restrict__ og)
{
    extern __shared__ char sm[];
    const u32 smb = cvta_smem(sm);
    const int tid = threadIdx.x, lane = tid & 31, wid = tid >> 5;

    const int tile = blockIdx.x;
    const int bh   = blockIdx.y;
    const size_t base = (size_t)bh * SEQ * Dh;
    const float* Qg = qg + base + (size_t)tile * BM * Dh;
    const float* Kg = kg + base;
    const float* Vg = vg + base;
    float*       Og = og + base + (size_t)tile * BM * Dh;
    const float scL = scg[bh] * LOG2E;

    // ---- prologue: Q (scale folded, split) + tile 0 ----
    #pragma unroll
    for (int p = 0; p < 8; p++) {
        int idx = tid + p * 256;
        int row = idx >> 4, ch = idx & 15;
        const float* s = Qg + (size_t)row * Dh + ch * 8;
        float4 a = *(const float4*)s;
        float4 b = *(const float4*)(s + 4);
        u32 h0, l0, h1, l1, h2, l2, h3, l3;
        split2(a.x * scL, a.y * scL, h0, l0); split2(a.z * scL, a.w * scL, h1, l1);
        split2(b.x * scL, b.y * scL, h2, l2); split2(b.z * scL, b.w * scL, h3, l3);
        u32 off = swoff(row, ch);
        *(uint4*)(sm + QH_OFF + off) = make_uint4(h0, h1, h2, h3);
        *(uint4*)(sm + QL_OFF + off) = make_uint4(l0, l1, l2, l3);
    }
    conv_k(Kg, sm + K_OFF, sm + K_OFF + 16384, tid);
    conv_v(Vg, sm + V_OFF, tid);
    __syncthreads();

    // ---- per-warp state ----
    float oacc[16][4];
    #pragma unroll
    for (int f = 0; f < 16; f++)
        #pragma unroll
        for (int j = 0; j < 4; j++) oacc[f][j] = 0.f;
    float mA = -1e30f, mB = -1e30f, lA = 0.f, lB = 0.f;

    const int wr0 = wid * 16;
    const int qrow = wr0 + (lane & 15);
    const int qchh = lane >> 4;
    const int kn   = (lane & 7) + ((lane >> 4) << 3);
    const int kchh = (lane >> 3) & 1;
    const int vkey = (lane & 7) + (((lane >> 3) & 1) << 3);
    const int vchh = lane >> 4;

    #pragma unroll 1
    for (int n = 0; n < NIT; n++) {
        const int buf = n & 1;
        const u32 khb = smb + K_OFF + buf * 32768;
        const u32 klb = khb + 16384;
        const u32 vhb = smb + V_OFF + buf * 16384;

        // ---- S = (Qh+Ql)(Kh+Kl)^T, 3 products ----
        float sacc[8][4];
        #pragma unroll
        for (int f = 0; f < 8; f++)
            #pragma unroll
            for (int j = 0; j < 4; j++) sacc[f][j] = 0.f;

        #pragma unroll
        for (int kk = 0; kk < 8; kk++) {
            u32 qoff = swoff(qrow, kk * 2 + qchh);
            u32 qh0, qh1, qh2, qh3, ql0, ql1, ql2, ql3;
            ldm4(smb + QH_OFF + qoff, qh0, qh1, qh2, qh3);
            ldm4(smb + QL_OFF + qoff, ql0, ql1, ql2, ql3);
            #pragma unroll
            for (int jp = 0; jp < 4; jp++) {
                u32 koff = swoff(jp * 16 + kn, kk * 2 + kchh);
                u32 kb0, kb1, kb2, kb3, lb0, lb1, lb2, lb3;
                ldm4(khb + koff, kb0, kb1, kb2, kb3);
                ldm4(klb + koff, lb0, lb1, lb2, lb3);
                mma(sacc[jp * 2],     qh0, qh1, qh2, qh3, kb0, kb1);
                mma(sacc[jp * 2],     qh0, qh1, qh2, qh3, lb0, lb1);
                mma(sacc[jp * 2],     ql0, ql1, ql2, ql3, kb0, kb1);
                mma(sacc[jp * 2 + 1], qh0, qh1, qh2, qh3, kb2, kb3);
                mma(sacc[jp * 2 + 1], qh0, qh1, qh2, qh3, lb2, lb3);
                mma(sacc[jp * 2 + 1], ql0, ql1, ql2, ql3, kb2, kb3);
            }
        }

        // ---- online softmax (log2 domain) ----
        float rmaxA = -1e30f, rmaxB = -1e30f;
        #pragma unroll
        for (int f = 0; f < 8; f++) {
            rmaxA = fmaxf(rmaxA, fmaxf(sacc[f][0], sacc[f][1]));
            rmaxB = fmaxf(rmaxB, fmaxf(sacc[f][2], sacc[f][3]));
        }
        rmaxA = fmaxf(rmaxA, __shfl_xor_sync(0xffffffffu, rmaxA, 1));
        rmaxA = fmaxf(rmaxA, __shfl_xor_sync(0xffffffffu, rmaxA, 2));
        rmaxB = fmaxf(rmaxB, __shfl_xor_sync(0xffffffffu, rmaxB, 1));
        rmaxB = fmaxf(rmaxB, __shfl_xor_sync(0xffffffffu, rmaxB, 2));

        float mnA = fmaxf(mA, rmaxA), mnB = fmaxf(mB, rmaxB);
        float aA = ex2f(mA - mnA), aB = ex2f(mB - mnB);
        mA = mnA; mB = mnB;

        u32 ph[4][4];
        float sA = 0.f, sB = 0.f;
        #pragma unroll
        for (int kk = 0; kk < 4; kk++) {
            float p0 = ex2f(sacc[2 * kk][0] - mnA);
            float p1 = ex2f(sacc[2 * kk][1] - mnA);
            float p2 = ex2f(sacc[2 * kk][2] - mnB);
            float p3 = ex2f(sacc[2 * kk][3] - mnB);
            float p4 = ex2f(sacc[2 * kk + 1][0] - mnA);
            float p5 = ex2f(sacc[2 * kk + 1][1] - mnA);
            float p6 = ex2f(sacc[2 * kk + 1][2] - mnB);
            float p7 = ex2f(sacc[2 * kk + 1][3] - mnB);
            sA += (p0 + p1) + (p4 + p5);
            sB += (p2 + p3) + (p6 + p7);
            ph[kk][0] = pack2(p0, p1);
            ph[kk][1] = pack2(p2, p3);
            ph[kk][2] = pack2(p4, p5);
            ph[kk][3] = pack2(p6, p7);
        }
        sA += __shfl_xor_sync(0xffffffffu, sA, 1);
        sA += __shfl_xor_sync(0xffffffffu, sA, 2);
        sB += __shfl_xor_sync(0xffffffffu, sB, 1);
        sB += __shfl_xor_sync(0xffffffffu, sB, 2);
        lA = lA * aA + sA;
        lB = lB * aB + sB;

        #pragma unroll
        for (int f = 0; f < 16; f++) {
            oacc[f][0] *= aA; oacc[f][1] *= aA;
            oacc[f][2] *= aB; oacc[f][3] *= aB;
        }

        // ---- O += Ph @ Vh (single product) ----
        #pragma unroll
        for (int kk = 0; kk < 4; kk++) {
            #pragma unroll
            for (int dp = 0; dp < 8; dp++) {
                u32 voff = swoff(kk * 16 + vkey, dp * 2 + vchh);
                u32 vb0, vb1, vb2, vb3;
                ldm4t(vhb + voff, vb0, vb1, vb2, vb3);
                mma(oacc[2 * dp],     ph[kk][0], ph[kk][1], ph[kk][2], ph[kk][3], vb0, vb1);
                mma(oacc[2 * dp + 1], ph[kk][0], ph[kk][1], ph[kk][2], ph[kk][3], vb2, vb3);
            }
        }

        // ---- convert next tile (overlaps other warps' compute; 1 sync/iter) ----
        if (n + 1 < NIT) {
            conv_k(Kg + (size_t)(n + 1) * BN * Dh,
                   sm + K_OFF + (buf ^ 1) * 32768,
                   sm + K_OFF + (buf ^ 1) * 32768 + 16384, tid);
            conv_v(Vg + (size_t)(n + 1) * BN * Dh,
                   sm + V_OFF + (buf ^ 1) * 16384, tid);
        }
        __syncthreads();
    }

    // ---- epilogue ----
    const float iA = 1.f / lA, iB = 1.f / lB;
    const int ra = wr0 + (lane >> 2);
    const int rb = ra + 8;
    const int cb = 2 * (lane & 3);
    #pragma unroll
    for (int f = 0; f < 16; f++) {
        float2 va; va.x = oacc[f][0] * iA; va.y = oacc[f][1] * iA;
        float2 vb; vb.x = oacc[f][2] * iB; vb.y = oacc[f][3] * iB;
        *(float2*)(Og + (size_t)ra * Dh + f * 8 + cb) = va;
        *(float2*)(Og + (size_t)rb * Dh + f * 8 + cb) = vb;
    }
}

extern "C" void kernel_launch(void* const* d_in, const int* in_sizes, int n_in,
                              void* d_out, int out_size)
{
    const float* q     = (const float*)d_in[0];
    const float* k     = (const float*)d_in[1];
    const float* v     = (const float*)d_in[2];
    const float* scale = (const float*)d_in[3];
    float* out = (float*)d_out;

    cudaFuncSetAttribute(attn_hmma, cudaFuncAttributeMaxDynamicSharedMemorySize, SMEM_BYTES);
    dim3 grid(SEQ / BM, 4 * 16);
    attn_hmma<<<grid, NT, SMEM_BYTES>>>(q, k, v, scale, out);
}